// round 5
// baseline (speedup 1.0000x reference)
#include <cuda_runtime.h>
#include <math.h>

#define BSZ   1024
#define NB    30
#define KNN   10
#define HID   128
#define EMB   64
#define NROWS (BSZ*NB)
#define P     34          // k_feat shared pitch
#define PM    68          // k_msg pitch: 68 floats = 272B, 16B-aligned rows -> LDS.128 OK
#define RMSG  64          // rows per k_msg block

typedef unsigned long long u64;

__device__ __forceinline__ float tanha(float x) {
    float y; asm("tanh.approx.f32 %0, %1;" : "=f"(y) : "f"(x)); return y;
}
__device__ __forceinline__ u64 pk(float x) {
    u64 d; asm("mov.b64 %0,{%1,%1};" : "=l"(d) : "f"(x)); return d;
}
__device__ __forceinline__ u64 fma2(u64 a, u64 b, u64 c) {
    u64 d; asm("fma.rn.f32x2 %0,%1,%2,%3;" : "=l"(d) : "l"(a), "l"(b), "l"(c)); return d;
}
__device__ __forceinline__ float2 up(u64 a) {
    float2 r; asm("mov.b64 {%0,%1},%2;" : "=f"(r.x), "=f"(r.y) : "l"(a)); return r;
}

// ---------------- constant: W_m2 (exactly 64KB) ----------------
__constant__ float4 c_Wm2[4096];   // [kk*32 + c4group]

// ---------------- device scratch ----------------
__device__ float g_cf[NB*EMB];
__device__ float g_Wcomb[192*256];
__device__ int   g_nbr[NROWS*KNN];
__device__ float g_A[NROWS*HID];
__device__ float g_C[NROWS*HID];

// ---------------- kernel 0: tiny precompute ----------------
__global__ void k_setup(const float* __restrict__ emb_tab,
                        const float* __restrict__ W_emb,
                        const float* __restrict__ b_emb,
                        const float* __restrict__ W_m1)
{
    int tid = blockIdx.x * blockDim.x + threadIdx.x;
    int stride = gridDim.x * blockDim.x;
    for (int idx = tid; idx < NB*EMB; idx += stride) {
        int n = idx / EMB, e = idx - n*EMB;
        int cat = n / (NB/3);
        float s = b_emb[e];
        for (int k = 0; k < EMB; k++)
            s += tanhf(emb_tab[cat*EMB + k]) * W_emb[k*EMB + e];
        g_cf[idx] = tanhf(s);
    }
    for (int idx = tid; idx < 192*256; idx += stride) {
        int k = idx >> 8, c = idx & 255;
        float v;
        if (c < 128) v = W_m1[k*128 + c] - W_m1[(192+k)*128 + c];
        else         v = W_m1[(192+k)*128 + (c-128)];
        g_Wcomb[idx] = v;
    }
}

// ---------------- kernel 1: per-batch KNN ----------------
__global__ void k_knn(const float* __restrict__ state_inp)
{
    __shared__ float px[NB], py[NB];
    int b = blockIdx.x, t = threadIdx.x;
    if (t < NB) { px[t] = state_inp[b*60 + 2*t]; py[t] = state_inp[b*60 + 2*t + 1]; }
    __syncthreads();
    if (t < NB) {
        float bd[KNN]; int bi[KNN];
        #pragma unroll
        for (int k = 0; k < KNN; k++) { bd[k] = 1e30f; bi[k] = 0; }
        float xi = px[t], yi = py[t];
        for (int j = 0; j < NB; j++) {
            if (j == t) continue;
            float dx = px[j] - xi, dy = py[j] - yi;
            float cd = dx*dx + dy*dy;
            int ci = j;
            #pragma unroll
            for (int k = 0; k < KNN; k++) {
                if (cd < bd[k]) {
                    float td = bd[k]; int ti = bi[k];
                    bd[k] = cd; bi[k] = ci; cd = td; ci = ti;
                }
            }
        }
        #pragma unroll
        for (int k = 0; k < KNN; k++) g_nbr[(b*NB + t)*KNN + k] = bi[k];
    }
}

// ---------------- kernel 2: feat MLP + A/C GEMM (32 rows/block) ----------------
__global__ __launch_bounds__(256, 2) void k_feat(
    const float* __restrict__ state_inp, const float* __restrict__ tar,
    const float* __restrict__ W_in1, const float* __restrict__ b_in1,
    const float* __restrict__ W_in2, const float* __restrict__ b_in2,
    const float* __restrict__ b_m1)
{
    __shared__ float s_in4[32][4];
    __shared__ float s_t[128][P];
    __shared__ float s_f[192][P];
    const int tid = threadIdx.x;
    const int row0 = blockIdx.x * 32;

    if (tid < 128) {
        int r = tid >> 2, q = tid & 3;
        int row = row0 + r;
        int b = row / NB, n = row - b*NB;
        float v = (q < 2) ? state_inp[b*60 + 2*n + q] : tanha(tar[row*2 + (q-2)]);
        s_in4[r][q] = v;
    }
    for (int idx = tid; idx < 32*EMB; idx += 256) {
        int r = idx & 31, e = idx >> 5;
        int n = (row0 + r) % NB;
        s_f[128 + e][r] = g_cf[n*EMB + e];
    }
    __syncthreads();

    // stage 1
    {
        const int c  = tid & 127;
        const int rh = tid >> 7;
        float w0 = W_in1[c], w1 = W_in1[128+c], w2 = W_in1[256+c], w3 = W_in1[384+c];
        float bb = b_in1[c];
        #pragma unroll
        for (int m = 0; m < 16; m++) {
            int r = rh*16 + m;
            float4 in = *reinterpret_cast<const float4*>(&s_in4[r][0]);
            s_t[c][r] = tanha(bb + w0*in.x + w1*in.y + w2*in.z + w3*in.w);
        }
    }
    __syncthreads();

    const int g  = tid >> 6;
    const int rb = g*8;

    // stage 2 (f32x2): 8 rows x 2 cols
    {
        const int c2 = tid & 63;
        u64 acc[4][2];
        #pragma unroll
        for (int q = 0; q < 4; q++) { acc[q][0] = 0ull; acc[q][1] = 0ull; }
        #pragma unroll 4
        for (int k = 0; k < 128; k++) {
            float2 w = *reinterpret_cast<const float2*>(&W_in2[k*128 + 2*c2]);
            u64 w0 = pk(w.x), w1 = pk(w.y);
            #pragma unroll
            for (int q = 0; q < 4; q++) {
                u64 tv = *reinterpret_cast<const u64*>(&s_t[k][rb + 2*q]);
                acc[q][0] = fma2(tv, w0, acc[q][0]);
                acc[q][1] = fma2(tv, w1, acc[q][1]);
            }
        }
        float2 bb = *reinterpret_cast<const float2*>(&b_in2[2*c2]);
        #pragma unroll
        for (int q = 0; q < 4; q++) {
            float2 a0 = up(acc[q][0]), a1 = up(acc[q][1]);
            s_f[2*c2  ][rb + 2*q]   = tanha(a0.x + bb.x);
            s_f[2*c2  ][rb + 2*q+1] = tanha(a0.y + bb.x);
            s_f[2*c2+1][rb + 2*q]   = tanha(a1.x + bb.y);
            s_f[2*c2+1][rb + 2*q+1] = tanha(a1.y + bb.y);
        }
    }
    __syncthreads();

    // stage 3 (f32x2): [C|A] = f192 @ Wcomb, 8 rows x 4 cols
    {
        const int c4 = tid & 63;
        u64 acc[4][4];
        #pragma unroll
        for (int q = 0; q < 4; q++)
            #pragma unroll
            for (int n = 0; n < 4; n++) acc[q][n] = 0ull;
        #pragma unroll 2
        for (int k = 0; k < 192; k++) {
            float4 w = *reinterpret_cast<const float4*>(&g_Wcomb[k*256 + 4*c4]);
            u64 w0 = pk(w.x), w1 = pk(w.y), w2 = pk(w.z), w3 = pk(w.w);
            #pragma unroll
            for (int q = 0; q < 4; q++) {
                u64 fv = *reinterpret_cast<const u64*>(&s_f[k][rb + 2*q]);
                acc[q][0] = fma2(fv, w0, acc[q][0]);
                acc[q][1] = fma2(fv, w1, acc[q][1]);
                acc[q][2] = fma2(fv, w2, acc[q][2]);
                acc[q][3] = fma2(fv, w3, acc[q][3]);
            }
        }
        if (c4 < 32) {
            float4 bb = *reinterpret_cast<const float4*>(&b_m1[4*c4]);
            #pragma unroll
            for (int q = 0; q < 4; q++) {
                float2 a0 = up(acc[q][0]), a1 = up(acc[q][1]), a2 = up(acc[q][2]), a3 = up(acc[q][3]);
                *reinterpret_cast<float4*>(&g_C[(row0+rb+2*q  )*128 + 4*c4]) =
                    make_float4(a0.x+bb.x, a1.x+bb.y, a2.x+bb.z, a3.x+bb.w);
                *reinterpret_cast<float4*>(&g_C[(row0+rb+2*q+1)*128 + 4*c4]) =
                    make_float4(a0.y+bb.x, a1.y+bb.y, a2.y+bb.z, a3.y+bb.w);
            }
        } else {
            int ca = 4*c4 - 128;
            #pragma unroll
            for (int q = 0; q < 4; q++) {
                float2 a0 = up(acc[q][0]), a1 = up(acc[q][1]), a2 = up(acc[q][2]), a3 = up(acc[q][3]);
                *reinterpret_cast<float4*>(&g_A[(row0+rb+2*q  )*128 + ca]) =
                    make_float4(a0.x, a1.x, a2.x, a3.x);
                *reinterpret_cast<float4*>(&g_A[(row0+rb+2*q+1)*128 + ca]) =
                    make_float4(a0.y, a1.y, a2.y, a3.y);
            }
        }
    }
}

// ---------------- kernel 3: edge msg, double-buffered + constant W_m2 ----------------
#define SM_BUF0 0
#define SM_BUF1 (128*PM)
#define SM_NB   (2*128*PM)
#define SMEM_MSG_BYTES ((2*128*PM + RMSG*KNN) * 4)

__global__ __launch_bounds__(256, 2) void k_msg(
    const float* __restrict__ tar,
    const float* __restrict__ b_m2,
    const float* __restrict__ W_a1, const float* __restrict__ b_a1,
    const float* __restrict__ W_a2, const float* __restrict__ b_a2,
    float* __restrict__ out)
{
    extern __shared__ float smem[];
    float* s_buf[2] = { smem + SM_BUF0, smem + SM_BUF1 };
    int*   s_nb = (int*)(smem + SM_NB);

    const int tid  = threadIdx.x;
    const int row0 = blockIdx.x * RMSG;

    for (int idx = tid; idx < RMSG*KNN; idx += 256) {
        int r = idx / KNN;
        int b = (row0 + r) / NB;
        s_nb[idx] = b*NB + g_nbr[row0*KNN + idx];
    }
    __syncthreads();

    const int cg = tid & 31;         // col group: cols 4cg..4cg+3
    const int c4 = cg * 4;
    const int g  = tid >> 5;         // 8 row groups
    const int rb = g * 8;            // rows rb..rb+7

    // build(0)
    {
        float* s_m = s_buf[0];
        #pragma unroll 8
        for (int it = 0; it < 32; it++) {
            int idx = tid + 256*it;
            int r = idx >> 7, j = idx & 127;
            float a = g_A[s_nb[r*KNN + 0]*128 + j];
            float c = g_C[(row0 + r)*128 + j];
            s_m[j*PM + r] = tanha(c + a);
        }
    }
    __syncthreads();

    float vmax[8][4];
    #pragma unroll
    for (int m = 0; m < 8; m++)
        #pragma unroll
        for (int n = 0; n < 4; n++) vmax[m][n] = -1e30f;

    for (int k = 0; k < KNN; k++) {
        // overlap: build(k+1) into other buffer (LDG latency hides under GEMM below)
        if (k + 1 < KNN) {
            float* s_n = s_buf[(k+1) & 1];
            #pragma unroll 8
            for (int it = 0; it < 32; it++) {
                int idx = tid + 256*it;
                int r = idx >> 7, j = idx & 127;
                float a = g_A[s_nb[r*KNN + k + 1]*128 + j];
                float c = g_C[(row0 + r)*128 + j];
                s_n[j*PM + r] = tanha(c + a);
            }
        }

        // GEMM(k): W from constant (no L1TEX), activations via LDS.128
        const float* s_m = s_buf[k & 1];
        u64 acc[4][4];
        #pragma unroll
        for (int q = 0; q < 4; q++)
            #pragma unroll
            for (int n = 0; n < 4; n++) acc[q][n] = 0ull;
        #pragma unroll 4
        for (int kk = 0; kk < 128; kk++) {
            float4 w = c_Wm2[kk*32 + cg];
            u64 w0 = pk(w.x), w1 = pk(w.y), w2 = pk(w.z), w3 = pk(w.w);
            float4 m0 = *reinterpret_cast<const float4*>(&s_m[kk*PM + rb]);
            float4 m1 = *reinterpret_cast<const float4*>(&s_m[kk*PM + rb + 4]);
            u64 r01 = reinterpret_cast<const u64*>(&m0)[0];
            u64 r23 = reinterpret_cast<const u64*>(&m0)[1];
            u64 r45 = reinterpret_cast<const u64*>(&m1)[0];
            u64 r67 = reinterpret_cast<const u64*>(&m1)[1];
            acc[0][0] = fma2(r01, w0, acc[0][0]);
            acc[0][1] = fma2(r01, w1, acc[0][1]);
            acc[0][2] = fma2(r01, w2, acc[0][2]);
            acc[0][3] = fma2(r01, w3, acc[0][3]);
            acc[1][0] = fma2(r23, w0, acc[1][0]);
            acc[1][1] = fma2(r23, w1, acc[1][1]);
            acc[1][2] = fma2(r23, w2, acc[1][2]);
            acc[1][3] = fma2(r23, w3, acc[1][3]);
            acc[2][0] = fma2(r45, w0, acc[2][0]);
            acc[2][1] = fma2(r45, w1, acc[2][1]);
            acc[2][2] = fma2(r45, w2, acc[2][2]);
            acc[2][3] = fma2(r45, w3, acc[2][3]);
            acc[3][0] = fma2(r67, w0, acc[3][0]);
            acc[3][1] = fma2(r67, w1, acc[3][1]);
            acc[3][2] = fma2(r67, w2, acc[3][2]);
            acc[3][3] = fma2(r67, w3, acc[3][3]);
        }
        #pragma unroll
        for (int q = 0; q < 4; q++)
            #pragma unroll
            for (int n = 0; n < 4; n++) {
                float2 v = up(acc[q][n]);
                vmax[2*q  ][n] = fmaxf(vmax[2*q  ][n], v.x);
                vmax[2*q+1][n] = fmaxf(vmax[2*q+1][n], v.y);
            }
        __syncthreads();
    }

    // x = tanh(max + b_m2) -> s_x (overlay buf0; last GEMM read buf1)
    float* s_x = s_buf[0];
    {
        float4 bb = *reinterpret_cast<const float4*>(&b_m2[c4]);
        #pragma unroll
        for (int m = 0; m < 8; m++) {
            s_x[(c4  )*PM + rb + m] = tanha(vmax[m][0] + bb.x);
            s_x[(c4+1)*PM + rb + m] = tanha(vmax[m][1] + bb.y);
            s_x[(c4+2)*PM + rb + m] = tanha(vmax[m][2] + bb.z);
            s_x[(c4+3)*PM + rb + m] = tanha(vmax[m][3] + bb.w);
        }
    }
    __syncthreads();

    // y = tanh(x @ W_a1 + b_a1) -> s_y (buf1)
    float* s_y = s_buf[1];
    {
        u64 acc[4][4];
        #pragma unroll
        for (int q = 0; q < 4; q++)
            #pragma unroll
            for (int n = 0; n < 4; n++) acc[q][n] = 0ull;
        #pragma unroll 4
        for (int kk = 0; kk < 128; kk++) {
            float4 w = *reinterpret_cast<const float4*>(&W_a1[kk*128 + c4]);
            u64 w0 = pk(w.x), w1 = pk(w.y), w2 = pk(w.z), w3 = pk(w.w);
            float4 m0 = *reinterpret_cast<const float4*>(&s_x[kk*PM + rb]);
            float4 m1 = *reinterpret_cast<const float4*>(&s_x[kk*PM + rb + 4]);
            u64 r01 = reinterpret_cast<const u64*>(&m0)[0];
            u64 r23 = reinterpret_cast<const u64*>(&m0)[1];
            u64 r45 = reinterpret_cast<const u64*>(&m1)[0];
            u64 r67 = reinterpret_cast<const u64*>(&m1)[1];
            acc[0][0] = fma2(r01, w0, acc[0][0]);
            acc[0][1] = fma2(r01, w1, acc[0][1]);
            acc[0][2] = fma2(r01, w2, acc[0][2]);
            acc[0][3] = fma2(r01, w3, acc[0][3]);
            acc[1][0] = fma2(r23, w0, acc[1][0]);
            acc[1][1] = fma2(r23, w1, acc[1][1]);
            acc[1][2] = fma2(r23, w2, acc[1][2]);
            acc[1][3] = fma2(r23, w3, acc[1][3]);
            acc[2][0] = fma2(r45, w0, acc[2][0]);
            acc[2][1] = fma2(r45, w1, acc[2][1]);
            acc[2][2] = fma2(r45, w2, acc[2][2]);
            acc[2][3] = fma2(r45, w3, acc[2][3]);
            acc[3][0] = fma2(r67, w0, acc[3][0]);
            acc[3][1] = fma2(r67, w1, acc[3][1]);
            acc[3][2] = fma2(r67, w2, acc[3][2]);
            acc[3][3] = fma2(r67, w3, acc[3][3]);
        }
        float4 bb = *reinterpret_cast<const float4*>(&b_a1[c4]);
        #pragma unroll
        for (int q = 0; q < 4; q++) {
            float2 a0 = up(acc[q][0]), a1 = up(acc[q][1]), a2 = up(acc[q][2]), a3 = up(acc[q][3]);
            s_y[(c4  )*PM + rb + 2*q]   = tanha(a0.x + bb.x);
            s_y[(c4  )*PM + rb + 2*q+1] = tanha(a0.y + bb.x);
            s_y[(c4+1)*PM + rb + 2*q]   = tanha(a1.x + bb.y);
            s_y[(c4+1)*PM + rb + 2*q+1] = tanha(a1.y + bb.y);
            s_y[(c4+2)*PM + rb + 2*q]   = tanha(a2.x + bb.z);
            s_y[(c4+2)*PM + rb + 2*q+1] = tanha(a2.y + bb.z);
            s_y[(c4+3)*PM + rb + 2*q]   = tanha(a3.x + bb.w);
            s_y[(c4+3)*PM + rb + 2*q+1] = tanha(a3.y + bb.w);
        }
    }
    __syncthreads();

    // final 128 -> 4, exact squashing
    {
        int r = tid >> 2, o = tid & 3;
        float s = b_a2[o];
        #pragma unroll 4
        for (int kk = 0; kk < 128; kk++) s += s_y[kk*PM + r] * W_a2[kk*4 + o];
        int row = row0 + r;
        int b = row / NB, n = row - b*NB;
        if (o < 2) {
            float tv = tar[row*2 + o];
            out[b*60 + 2*n + o] = 0.3f*tanhf(s) + 0.3f*tanhf(tv);
        } else {
            float t = tanhf(s);
            float ls = 3.5f*t - 1.5f;
            out[BSZ*60 + b*60 + 2*n + (o-2)] = expf(ls);
        }
    }
}

// ---------------- launch ----------------
extern "C" void kernel_launch(void* const* d_in, const int* in_sizes, int n_in,
                              void* d_out, int out_size)
{
    const float* state_inp = (const float*)d_in[0];
    const float* tar       = (const float*)d_in[1];
    const float* W_in1     = (const float*)d_in[2];
    const float* b_in1     = (const float*)d_in[3];
    const float* W_in2     = (const float*)d_in[4];
    const float* b_in2     = (const float*)d_in[5];
    const float* emb_tab   = (const float*)d_in[6];
    const float* W_emb     = (const float*)d_in[7];
    const float* b_emb     = (const float*)d_in[8];
    const float* W_m1      = (const float*)d_in[9];
    const float* b_m1      = (const float*)d_in[10];
    const float* W_m2      = (const float*)d_in[11];
    const float* b_m2      = (const float*)d_in[12];
    const float* W_a1      = (const float*)d_in[13];
    const float* b_a1      = (const float*)d_in[14];
    const float* W_a2      = (const float*)d_in[15];
    const float* b_a2      = (const float*)d_in[16];
    float* out = (float*)d_out;

    cudaFuncSetAttribute(k_msg, cudaFuncAttributeMaxDynamicSharedMemorySize, SMEM_MSG_BYTES);
    cudaMemcpyToSymbolAsync(c_Wm2, W_m2, 128*128*sizeof(float), 0,
                            cudaMemcpyDeviceToDevice, 0);

    k_setup<<<64, 256>>>(emb_tab, W_emb, b_emb, W_m1);
    k_knn<<<BSZ, 32>>>(state_inp);
    k_feat<<<NROWS/32, 256>>>(state_inp, tar, W_in1, b_in1, W_in2, b_in2, b_m1);
    k_msg<<<NROWS/RMSG, 256, SMEM_MSG_BYTES>>>(tar, b_m2, W_a1, b_a1, W_a2, b_a2, out);
}

// round 6
// speedup vs baseline: 6.2213x; 6.2213x over previous
#include <cuda_runtime.h>
#include <math.h>

#define BSZ   1024
#define NB    30
#define KNN   10
#define HID   128
#define EMB   64
#define NROWS (BSZ*NB)
#define P     34          // k_feat shared pitch
#define PM    36          // k_msg pitch: 36 floats -> 16B-aligned rows, LDS.128 OK
#define RMSG  32          // rows per k_msg block

typedef unsigned long long u64;

__device__ __forceinline__ float tanha(float x) {
    float y; asm("tanh.approx.f32 %0, %1;" : "=f"(y) : "f"(x)); return y;
}
__device__ __forceinline__ u64 pk(float x) {
    u64 d; asm("mov.b64 %0,{%1,%1};" : "=l"(d) : "f"(x)); return d;
}
__device__ __forceinline__ u64 fma2(u64 a, u64 b, u64 c) {
    u64 d; asm("fma.rn.f32x2 %0,%1,%2,%3;" : "=l"(d) : "l"(a), "l"(b), "l"(c)); return d;
}
__device__ __forceinline__ float2 up(u64 a) {
    float2 r; asm("mov.b64 {%0,%1},%2;" : "=f"(r.x), "=f"(r.y) : "l"(a)); return r;
}

// ---------------- device scratch ----------------
__device__ float g_cf[NB*EMB];
__device__ float g_Wcomb[192*256];
__device__ int   g_nbr[NROWS*KNN];
__device__ float g_A[NROWS*HID];
__device__ float g_C[NROWS*HID];

// ---------------- kernel 0: tiny precompute ----------------
__global__ void k_setup(const float* __restrict__ emb_tab,
                        const float* __restrict__ W_emb,
                        const float* __restrict__ b_emb,
                        const float* __restrict__ W_m1)
{
    int tid = blockIdx.x * blockDim.x + threadIdx.x;
    int stride = gridDim.x * blockDim.x;
    for (int idx = tid; idx < NB*EMB; idx += stride) {
        int n = idx / EMB, e = idx - n*EMB;
        int cat = n / (NB/3);
        float s = b_emb[e];
        for (int k = 0; k < EMB; k++)
            s += tanhf(emb_tab[cat*EMB + k]) * W_emb[k*EMB + e];
        g_cf[idx] = tanhf(s);
    }
    for (int idx = tid; idx < 192*256; idx += stride) {
        int k = idx >> 8, c = idx & 255;
        float v;
        if (c < 128) v = W_m1[k*128 + c] - W_m1[(192+k)*128 + c];
        else         v = W_m1[(192+k)*128 + (c-128)];
        g_Wcomb[idx] = v;
    }
}

// ---------------- kernel 1: per-batch KNN ----------------
__global__ void k_knn(const float* __restrict__ state_inp)
{
    __shared__ float px[NB], py[NB];
    int b = blockIdx.x, t = threadIdx.x;
    if (t < NB) { px[t] = state_inp[b*60 + 2*t]; py[t] = state_inp[b*60 + 2*t + 1]; }
    __syncthreads();
    if (t < NB) {
        float bd[KNN]; int bi[KNN];
        #pragma unroll
        for (int k = 0; k < KNN; k++) { bd[k] = 1e30f; bi[k] = 0; }
        float xi = px[t], yi = py[t];
        for (int j = 0; j < NB; j++) {
            if (j == t) continue;
            float dx = px[j] - xi, dy = py[j] - yi;
            float cd = dx*dx + dy*dy;
            int ci = j;
            #pragma unroll
            for (int k = 0; k < KNN; k++) {
                if (cd < bd[k]) {
                    float td = bd[k]; int ti = bi[k];
                    bd[k] = cd; bi[k] = ci; cd = td; ci = ti;
                }
            }
        }
        #pragma unroll
        for (int k = 0; k < KNN; k++) g_nbr[(b*NB + t)*KNN + k] = bi[k];
    }
}

// ---------------- kernel 2: feat MLP + A/C GEMM (32 rows/block) ----------------
__global__ __launch_bounds__(256, 2) void k_feat(
    const float* __restrict__ state_inp, const float* __restrict__ tar,
    const float* __restrict__ W_in1, const float* __restrict__ b_in1,
    const float* __restrict__ W_in2, const float* __restrict__ b_in2,
    const float* __restrict__ b_m1)
{
    __shared__ float s_in4[32][4];
    __shared__ float s_t[128][P];
    __shared__ float s_f[192][P];
    const int tid = threadIdx.x;
    const int row0 = blockIdx.x * 32;

    if (tid < 128) {
        int r = tid >> 2, q = tid & 3;
        int row = row0 + r;
        int b = row / NB, n = row - b*NB;
        float v = (q < 2) ? state_inp[b*60 + 2*n + q] : tanha(tar[row*2 + (q-2)]);
        s_in4[r][q] = v;
    }
    for (int idx = tid; idx < 32*EMB; idx += 256) {
        int r = idx & 31, e = idx >> 5;
        int n = (row0 + r) % NB;
        s_f[128 + e][r] = g_cf[n*EMB + e];
    }
    __syncthreads();

    // stage 1
    {
        const int c  = tid & 127;
        const int rh = tid >> 7;
        float w0 = W_in1[c], w1 = W_in1[128+c], w2 = W_in1[256+c], w3 = W_in1[384+c];
        float bb = b_in1[c];
        #pragma unroll
        for (int m = 0; m < 16; m++) {
            int r = rh*16 + m;
            float4 in = *reinterpret_cast<const float4*>(&s_in4[r][0]);
            s_t[c][r] = tanha(bb + w0*in.x + w1*in.y + w2*in.z + w3*in.w);
        }
    }
    __syncthreads();

    const int g  = tid >> 6;
    const int rb = g*8;

    // stage 2 (f32x2): 8 rows x 2 cols
    {
        const int c2 = tid & 63;
        u64 acc[4][2];
        #pragma unroll
        for (int q = 0; q < 4; q++) { acc[q][0] = 0ull; acc[q][1] = 0ull; }
        #pragma unroll 4
        for (int k = 0; k < 128; k++) {
            float2 w = *reinterpret_cast<const float2*>(&W_in2[k*128 + 2*c2]);
            u64 w0 = pk(w.x), w1 = pk(w.y);
            #pragma unroll
            for (int q = 0; q < 4; q++) {
                u64 tv = *reinterpret_cast<const u64*>(&s_t[k][rb + 2*q]);
                acc[q][0] = fma2(tv, w0, acc[q][0]);
                acc[q][1] = fma2(tv, w1, acc[q][1]);
            }
        }
        float2 bb = *reinterpret_cast<const float2*>(&b_in2[2*c2]);
        #pragma unroll
        for (int q = 0; q < 4; q++) {
            float2 a0 = up(acc[q][0]), a1 = up(acc[q][1]);
            s_f[2*c2  ][rb + 2*q]   = tanha(a0.x + bb.x);
            s_f[2*c2  ][rb + 2*q+1] = tanha(a0.y + bb.x);
            s_f[2*c2+1][rb + 2*q]   = tanha(a1.x + bb.y);
            s_f[2*c2+1][rb + 2*q+1] = tanha(a1.y + bb.y);
        }
    }
    __syncthreads();

    // stage 3 (f32x2): [C|A] = f192 @ Wcomb, 8 rows x 4 cols
    {
        const int c4 = tid & 63;
        u64 acc[4][4];
        #pragma unroll
        for (int q = 0; q < 4; q++)
            #pragma unroll
            for (int n = 0; n < 4; n++) acc[q][n] = 0ull;
        #pragma unroll 2
        for (int k = 0; k < 192; k++) {
            float4 w = *reinterpret_cast<const float4*>(&g_Wcomb[k*256 + 4*c4]);
            u64 w0 = pk(w.x), w1 = pk(w.y), w2 = pk(w.z), w3 = pk(w.w);
            #pragma unroll
            for (int q = 0; q < 4; q++) {
                u64 fv = *reinterpret_cast<const u64*>(&s_f[k][rb + 2*q]);
                acc[q][0] = fma2(fv, w0, acc[q][0]);
                acc[q][1] = fma2(fv, w1, acc[q][1]);
                acc[q][2] = fma2(fv, w2, acc[q][2]);
                acc[q][3] = fma2(fv, w3, acc[q][3]);
            }
        }
        if (c4 < 32) {
            float4 bb = *reinterpret_cast<const float4*>(&b_m1[4*c4]);
            #pragma unroll
            for (int q = 0; q < 4; q++) {
                float2 a0 = up(acc[q][0]), a1 = up(acc[q][1]), a2 = up(acc[q][2]), a3 = up(acc[q][3]);
                *reinterpret_cast<float4*>(&g_C[(row0+rb+2*q  )*128 + 4*c4]) =
                    make_float4(a0.x+bb.x, a1.x+bb.y, a2.x+bb.z, a3.x+bb.w);
                *reinterpret_cast<float4*>(&g_C[(row0+rb+2*q+1)*128 + 4*c4]) =
                    make_float4(a0.y+bb.x, a1.y+bb.y, a2.y+bb.z, a3.y+bb.w);
            }
        } else {
            int ca = 4*c4 - 128;
            #pragma unroll
            for (int q = 0; q < 4; q++) {
                float2 a0 = up(acc[q][0]), a1 = up(acc[q][1]), a2 = up(acc[q][2]), a3 = up(acc[q][3]);
                *reinterpret_cast<float4*>(&g_A[(row0+rb+2*q  )*128 + ca]) =
                    make_float4(a0.x, a1.x, a2.x, a3.x);
                *reinterpret_cast<float4*>(&g_A[(row0+rb+2*q+1)*128 + ca]) =
                    make_float4(a0.y, a1.y, a2.y, a3.y);
            }
        }
    }
}

// ---------------- kernel 3: edge msg, all-smem build, 32 rows/block, 3 CTAs/SM ----------------
// dynamic smem layout (floats):
#define OF_A   0                   // s_A: 60 rows x 128  (A for the 2 batches this block touches)
#define OF_C   (60*128)            // s_C: 32 rows x 128
#define OF_M   (OF_C + 32*128)     // s_m: 128 x PM  (transposed tanh(C+A); reused as s_x/s_y staging)
#define OF_NB  (OF_M + 128*PM)     // s_nb: RMSG*KNN ints
#define SMEM_MSG_FLOATS (OF_NB + RMSG*KNN)
#define SMEM_MSG_BYTES  (SMEM_MSG_FLOATS * 4)

__global__ __launch_bounds__(256, 3) void k_msg(
    const float* __restrict__ tar,
    const float* __restrict__ W_m2, const float* __restrict__ b_m2,
    const float* __restrict__ W_a1, const float* __restrict__ b_a1,
    const float* __restrict__ W_a2, const float* __restrict__ b_a2,
    float* __restrict__ out)
{
    extern __shared__ float smem[];
    float* s_A  = smem + OF_A;
    float* s_C  = smem + OF_C;
    float* s_m  = smem + OF_M;
    int*   s_nb = (int*)(smem + OF_NB);

    const int tid  = threadIdx.x;
    const int row0 = blockIdx.x * RMSG;
    const int b0   = row0 / NB;

    // preload A for batches b0, b0+1 (60 rows), C for own 32 rows -- float4 coalesced
    {
        const float4* gA = reinterpret_cast<const float4*>(&g_A[b0*NB*128]);
        float4* sA = reinterpret_cast<float4*>(s_A);
        #pragma unroll
        for (int i = tid; i < 60*32; i += 256) sA[i] = gA[i];
        const float4* gC = reinterpret_cast<const float4*>(&g_C[row0*128]);
        float4* sC = reinterpret_cast<float4*>(s_C);
        #pragma unroll
        for (int i = tid; i < 32*32; i += 256) sC[i] = gC[i];
    }
    for (int idx = tid; idx < RMSG*KNN; idx += 256) {
        int r = idx / KNN;
        int b = (row0 + r) / NB;
        s_nb[idx] = (b - b0)*NB + g_nbr[row0*KNN + idx];   // local row in s_A
    }
    __syncthreads();

    const int c2 = tid & 63;          // cols 2c2, 2c2+1
    const int g  = tid >> 6;          // 4 row groups
    const int rb = g * 8;             // rows rb..rb+7

    float vmax[8][2];
    #pragma unroll
    for (int m = 0; m < 8; m++) { vmax[m][0] = -1e30f; vmax[m][1] = -1e30f; }

    for (int k = 0; k < KNN; k++) {
        // build m = tanh(C_i + A_j) -> s_m transposed [j][r]   (pure shared ops)
        #pragma unroll
        for (int it = 0; it < 16; it++) {
            int idx = tid + 256*it;
            int r = idx >> 7, j = idx & 127;
            float a = s_A[s_nb[r*KNN + k]*128 + j];
            float c = s_C[r*128 + j];
            s_m[j*PM + r] = tanha(c + a);
        }
        __syncthreads();

        u64 acc[4][2];
        #pragma unroll
        for (int q = 0; q < 4; q++) { acc[q][0] = 0ull; acc[q][1] = 0ull; }
        #pragma unroll 4
        for (int kk = 0; kk < 128; kk++) {
            float2 w = *reinterpret_cast<const float2*>(&W_m2[kk*128 + 2*c2]);
            u64 w0 = pk(w.x), w1 = pk(w.y);
            float4 m0 = *reinterpret_cast<const float4*>(&s_m[kk*PM + rb]);
            float4 m1 = *reinterpret_cast<const float4*>(&s_m[kk*PM + rb + 4]);
            u64 r01 = reinterpret_cast<const u64*>(&m0)[0];
            u64 r23 = reinterpret_cast<const u64*>(&m0)[1];
            u64 r45 = reinterpret_cast<const u64*>(&m1)[0];
            u64 r67 = reinterpret_cast<const u64*>(&m1)[1];
            acc[0][0] = fma2(r01, w0, acc[0][0]);  acc[0][1] = fma2(r01, w1, acc[0][1]);
            acc[1][0] = fma2(r23, w0, acc[1][0]);  acc[1][1] = fma2(r23, w1, acc[1][1]);
            acc[2][0] = fma2(r45, w0, acc[2][0]);  acc[2][1] = fma2(r45, w1, acc[2][1]);
            acc[3][0] = fma2(r67, w0, acc[3][0]);  acc[3][1] = fma2(r67, w1, acc[3][1]);
        }
        #pragma unroll
        for (int q = 0; q < 4; q++) {
            float2 v0 = up(acc[q][0]), v1 = up(acc[q][1]);
            vmax[2*q  ][0] = fmaxf(vmax[2*q  ][0], v0.x);
            vmax[2*q+1][0] = fmaxf(vmax[2*q+1][0], v0.y);
            vmax[2*q  ][1] = fmaxf(vmax[2*q  ][1], v1.x);
            vmax[2*q+1][1] = fmaxf(vmax[2*q+1][1], v1.y);
        }
        __syncthreads();
    }

    // x = tanh(max + b_m2) -> s_m (reuse as s_x, transposed [col][row])
    {
        float2 bb = *reinterpret_cast<const float2*>(&b_m2[2*c2]);
        #pragma unroll
        for (int m = 0; m < 8; m++) {
            s_m[(2*c2  )*PM + rb + m] = tanha(vmax[m][0] + bb.x);
            s_m[(2*c2+1)*PM + rb + m] = tanha(vmax[m][1] + bb.y);
        }
    }
    __syncthreads();

    // y = tanh(x @ W_a1 + b_a1) -> s_A (reuse as s_y)
    float* s_y = s_A;
    {
        u64 acc[4][2];
        #pragma unroll
        for (int q = 0; q < 4; q++) { acc[q][0] = 0ull; acc[q][1] = 0ull; }
        #pragma unroll 4
        for (int kk = 0; kk < 128; kk++) {
            float2 w = *reinterpret_cast<const float2*>(&W_a1[kk*128 + 2*c2]);
            u64 w0 = pk(w.x), w1 = pk(w.y);
            float4 m0 = *reinterpret_cast<const float4*>(&s_m[kk*PM + rb]);
            float4 m1 = *reinterpret_cast<const float4*>(&s_m[kk*PM + rb + 4]);
            u64 r01 = reinterpret_cast<const u64*>(&m0)[0];
            u64 r23 = reinterpret_cast<const u64*>(&m0)[1];
            u64 r45 = reinterpret_cast<const u64*>(&m1)[0];
            u64 r67 = reinterpret_cast<const u64*>(&m1)[1];
            acc[0][0] = fma2(r01, w0, acc[0][0]);  acc[0][1] = fma2(r01, w1, acc[0][1]);
            acc[1][0] = fma2(r23, w0, acc[1][0]);  acc[1][1] = fma2(r23, w1, acc[1][1]);
            acc[2][0] = fma2(r45, w0, acc[2][0]);  acc[2][1] = fma2(r45, w1, acc[2][1]);
            acc[3][0] = fma2(r67, w0, acc[3][0]);  acc[3][1] = fma2(r67, w1, acc[3][1]);
        }
        __syncthreads();   // s_m (x) fully consumed before overwriting s_y? (s_y is s_A, distinct) -- barrier orders y writes vs final reads
        float2 bb = *reinterpret_cast<const float2*>(&b_a1[2*c2]);
        #pragma unroll
        for (int q = 0; q < 4; q++) {
            float2 a0 = up(acc[q][0]), a1 = up(acc[q][1]);
            s_y[(2*c2  )*PM + rb + 2*q]   = tanha(a0.x + bb.x);
            s_y[(2*c2  )*PM + rb + 2*q+1] = tanha(a0.y + bb.x);
            s_y[(2*c2+1)*PM + rb + 2*q]   = tanha(a1.x + bb.y);
            s_y[(2*c2+1)*PM + rb + 2*q+1] = tanha(a1.y + bb.y);
        }
    }
    __syncthreads();

    // final 128 -> 4, exact squashing (32 rows x 4 outs = 128 threads)
    if (tid < 128) {
        int r = tid >> 2, o = tid & 3;
        float s = b_a2[o];
        #pragma unroll 4
        for (int kk = 0; kk < 128; kk++) s += s_y[kk*PM + r] * W_a2[kk*4 + o];
        int row = row0 + r;
        int b = row / NB, n = row - b*NB;
        if (o < 2) {
            float tv = tar[row*2 + o];
            out[b*60 + 2*n + o] = 0.3f*tanhf(s) + 0.3f*tanhf(tv);
        } else {
            float t = tanhf(s);
            float ls = 3.5f*t - 1.5f;
            out[BSZ*60 + b*60 + 2*n + (o-2)] = expf(ls);
        }
    }
}

// ---------------- launch ----------------
extern "C" void kernel_launch(void* const* d_in, const int* in_sizes, int n_in,
                              void* d_out, int out_size)
{
    const float* state_inp = (const float*)d_in[0];
    const float* tar       = (const float*)d_in[1];
    const float* W_in1     = (const float*)d_in[2];
    const float* b_in1     = (const float*)d_in[3];
    const float* W_in2     = (const float*)d_in[4];
    const float* b_in2     = (const float*)d_in[5];
    const float* emb_tab   = (const float*)d_in[6];
    const float* W_emb     = (const float*)d_in[7];
    const float* b_emb     = (const float*)d_in[8];
    const float* W_m1      = (const float*)d_in[9];
    const float* b_m1      = (const float*)d_in[10];
    const float* W_m2      = (const float*)d_in[11];
    const float* b_m2      = (const float*)d_in[12];
    const float* W_a1      = (const float*)d_in[13];
    const float* b_a1      = (const float*)d_in[14];
    const float* W_a2      = (const float*)d_in[15];
    const float* b_a2      = (const float*)d_in[16];
    float* out = (float*)d_out;

    cudaFuncSetAttribute(k_msg, cudaFuncAttributeMaxDynamicSharedMemorySize, SMEM_MSG_BYTES);

    k_setup<<<64, 256>>>(emb_tab, W_emb, b_emb, W_m1);
    k_knn<<<BSZ, 32>>>(state_inp);
    k_feat<<<NROWS/32, 256>>>(state_inp, tar, W_in1, b_in1, W_in2, b_in2, b_m1);
    k_msg<<<NROWS/RMSG, 256, SMEM_MSG_BYTES>>>(tar, W_m2, b_m2, W_a1, b_a1, W_a2, b_a2, out);
}

// round 8
// speedup vs baseline: 14.0508x; 2.2585x over previous
#include <cuda_runtime.h>
#include <math.h>

#define BSZ   1024
#define NB    30
#define KNN   10
#define HID   128
#define EMB   64
#define NROWS (BSZ*NB)
#define P     34
#define RMSG  64          // rows per k_msg block
#define PK    132         // s_m pitch (A operand / y) : bank-conflict-free A frags
#define PB    136         // s_B pitch : bank-conflict-free B frags

typedef unsigned long long u64;

__device__ __forceinline__ float tanha(float x) {
    float y; asm("tanh.approx.f32 %0, %1;" : "=f"(y) : "f"(x)); return y;
}
__device__ __forceinline__ u64 pk(float x) {
    u64 d; asm("mov.b64 %0,{%1,%1};" : "=l"(d) : "f"(x)); return d;
}
__device__ __forceinline__ u64 fma2(u64 a, u64 b, u64 c) {
    u64 d; asm("fma.rn.f32x2 %0,%1,%2,%3;" : "=l"(d) : "l"(a), "l"(b), "l"(c)); return d;
}
__device__ __forceinline__ float2 up(u64 a) {
    float2 r; asm("mov.b64 {%0,%1},%2;" : "=f"(r.x), "=f"(r.y) : "l"(a)); return r;
}
__device__ __forceinline__ unsigned tf32r(float x) {
    unsigned r; asm("cvt.rna.tf32.f32 %0, %1;" : "=r"(r) : "f"(x)); return r;
}

#define MMA_TF32(d0,d1,d2,d3,a0,a1,a2,a3,b0,b1) \
    asm volatile("mma.sync.aligned.m16n8k8.row.col.f32.tf32.tf32.f32 " \
        "{%0,%1,%2,%3},{%4,%5,%6,%7},{%8,%9},{%0,%1,%2,%3};" \
        : "+f"(d0),"+f"(d1),"+f"(d2),"+f"(d3) \
        : "r"(a0),"r"(a1),"r"(a2),"r"(a3),"r"(b0),"r"(b1))

// ---------------- device scratch ----------------
__device__ float g_cf[NB*EMB];
__device__ float g_Wcomb[192*256];
__device__ int   g_nbr[NROWS*KNN];
__device__ float g_A[NROWS*HID];
__device__ float g_C[NROWS*HID];

// ---------------- kernel 0: tiny precompute ----------------
__global__ void k_setup(const float* __restrict__ emb_tab,
                        const float* __restrict__ W_emb,
                        const float* __restrict__ b_emb,
                        const float* __restrict__ W_m1)
{
    int tid = blockIdx.x * blockDim.x + threadIdx.x;
    int stride = gridDim.x * blockDim.x;
    for (int idx = tid; idx < NB*EMB; idx += stride) {
        int n = idx / EMB, e = idx - n*EMB;
        int cat = n / (NB/3);
        float s = b_emb[e];
        for (int k = 0; k < EMB; k++)
            s += tanhf(emb_tab[cat*EMB + k]) * W_emb[k*EMB + e];
        g_cf[idx] = tanhf(s);
    }
    for (int idx = tid; idx < 192*256; idx += stride) {
        int k = idx >> 8, c = idx & 255;
        float v;
        if (c < 128) v = W_m1[k*128 + c] - W_m1[(192+k)*128 + c];
        else         v = W_m1[(192+k)*128 + (c-128)];
        g_Wcomb[idx] = v;
    }
}

// ---------------- kernel 1: per-batch KNN ----------------
__global__ void k_knn(const float* __restrict__ state_inp)
{
    __shared__ float px[NB], py[NB];
    int b = blockIdx.x, t = threadIdx.x;
    if (t < NB) { px[t] = state_inp[b*60 + 2*t]; py[t] = state_inp[b*60 + 2*t + 1]; }
    __syncthreads();
    if (t < NB) {
        float bd[KNN]; int bi[KNN];
        #pragma unroll
        for (int k = 0; k < KNN; k++) { bd[k] = 1e30f; bi[k] = 0; }
        float xi = px[t], yi = py[t];
        for (int j = 0; j < NB; j++) {
            if (j == t) continue;
            float dx = px[j] - xi, dy = py[j] - yi;
            float cd = dx*dx + dy*dy;
            int ci = j;
            #pragma unroll
            for (int k = 0; k < KNN; k++) {
                if (cd < bd[k]) {
                    float td = bd[k]; int ti = bi[k];
                    bd[k] = cd; bi[k] = ci; cd = td; ci = ti;
                }
            }
        }
        #pragma unroll
        for (int k = 0; k < KNN; k++) g_nbr[(b*NB + t)*KNN + k] = bi[k];
    }
}

// ---------------- kernel 2: feat MLP + A/C GEMM (unchanged) ----------------
__global__ __launch_bounds__(256, 2) void k_feat(
    const float* __restrict__ state_inp, const float* __restrict__ tar,
    const float* __restrict__ W_in1, const float* __restrict__ b_in1,
    const float* __restrict__ W_in2, const float* __restrict__ b_in2,
    const float* __restrict__ b_m1)
{
    __shared__ float s_in4[32][4];
    __shared__ float s_t[128][P];
    __shared__ float s_f[192][P];
    const int tid = threadIdx.x;
    const int row0 = blockIdx.x * 32;

    if (tid < 128) {
        int r = tid >> 2, q = tid & 3;
        int row = row0 + r;
        int b = row / NB, n = row - b*NB;
        float v = (q < 2) ? state_inp[b*60 + 2*n + q] : tanha(tar[row*2 + (q-2)]);
        s_in4[r][q] = v;
    }
    for (int idx = tid; idx < 32*EMB; idx += 256) {
        int r = idx & 31, e = idx >> 5;
        int n = (row0 + r) % NB;
        s_f[128 + e][r] = g_cf[n*EMB + e];
    }
    __syncthreads();

    {
        const int c  = tid & 127;
        const int rh = tid >> 7;
        float w0 = W_in1[c], w1 = W_in1[128+c], w2 = W_in1[256+c], w3 = W_in1[384+c];
        float bb = b_in1[c];
        #pragma unroll
        for (int m = 0; m < 16; m++) {
            int r = rh*16 + m;
            float4 in = *reinterpret_cast<const float4*>(&s_in4[r][0]);
            s_t[c][r] = tanha(bb + w0*in.x + w1*in.y + w2*in.z + w3*in.w);
        }
    }
    __syncthreads();

    const int g  = tid >> 6;
    const int rb = g*8;

    {
        const int c2 = tid & 63;
        u64 acc[4][2];
        #pragma unroll
        for (int q = 0; q < 4; q++) { acc[q][0] = 0ull; acc[q][1] = 0ull; }
        #pragma unroll 4
        for (int k = 0; k < 128; k++) {
            float2 w = *reinterpret_cast<const float2*>(&W_in2[k*128 + 2*c2]);
            u64 w0 = pk(w.x), w1 = pk(w.y);
            #pragma unroll
            for (int q = 0; q < 4; q++) {
                u64 tv = *reinterpret_cast<const u64*>(&s_t[k][rb + 2*q]);
                acc[q][0] = fma2(tv, w0, acc[q][0]);
                acc[q][1] = fma2(tv, w1, acc[q][1]);
            }
        }
        float2 bb = *reinterpret_cast<const float2*>(&b_in2[2*c2]);
        #pragma unroll
        for (int q = 0; q < 4; q++) {
            float2 a0 = up(acc[q][0]), a1 = up(acc[q][1]);
            s_f[2*c2  ][rb + 2*q]   = tanha(a0.x + bb.x);
            s_f[2*c2  ][rb + 2*q+1] = tanha(a0.y + bb.x);
            s_f[2*c2+1][rb + 2*q]   = tanha(a1.x + bb.y);
            s_f[2*c2+1][rb + 2*q+1] = tanha(a1.y + bb.y);
        }
    }
    __syncthreads();

    {
        const int c4 = tid & 63;
        u64 acc[4][4];
        #pragma unroll
        for (int q = 0; q < 4; q++)
            #pragma unroll
            for (int n = 0; n < 4; n++) acc[q][n] = 0ull;
        #pragma unroll 2
        for (int k = 0; k < 192; k++) {
            float4 w = *reinterpret_cast<const float4*>(&g_Wcomb[k*256 + 4*c4]);
            u64 w0 = pk(w.x), w1 = pk(w.y), w2 = pk(w.z), w3 = pk(w.w);
            #pragma unroll
            for (int q = 0; q < 4; q++) {
                u64 fv = *reinterpret_cast<const u64*>(&s_f[k][rb + 2*q]);
                acc[q][0] = fma2(fv, w0, acc[q][0]);
                acc[q][1] = fma2(fv, w1, acc[q][1]);
                acc[q][2] = fma2(fv, w2, acc[q][2]);
                acc[q][3] = fma2(fv, w3, acc[q][3]);
            }
        }
        if (c4 < 32) {
            float4 bb = *reinterpret_cast<const float4*>(&b_m1[4*c4]);
            #pragma unroll
            for (int q = 0; q < 4; q++) {
                float2 a0 = up(acc[q][0]), a1 = up(acc[q][1]), a2 = up(acc[q][2]), a3 = up(acc[q][3]);
                *reinterpret_cast<float4*>(&g_C[(row0+rb+2*q  )*128 + 4*c4]) =
                    make_float4(a0.x+bb.x, a1.x+bb.y, a2.x+bb.z, a3.x+bb.w);
                *reinterpret_cast<float4*>(&g_C[(row0+rb+2*q+1)*128 + 4*c4]) =
                    make_float4(a0.y+bb.x, a1.y+bb.y, a2.y+bb.z, a3.y+bb.w);
            }
        } else {
            int ca = 4*c4 - 128;
            #pragma unroll
            for (int q = 0; q < 4; q++) {
                float2 a0 = up(acc[q][0]), a1 = up(acc[q][1]), a2 = up(acc[q][2]), a3 = up(acc[q][3]);
                *reinterpret_cast<float4*>(&g_A[(row0+rb+2*q  )*128 + ca]) =
                    make_float4(a0.x, a1.x, a2.x, a3.x);
                *reinterpret_cast<float4*>(&g_A[(row0+rb+2*q+1)*128 + ca]) =
                    make_float4(a0.y, a1.y, a2.y, a3.y);
            }
        }
    }
}

// ---------------- kernel 3: edge msg via mma.sync tf32 (64 rows/block) ----------------
// dynamic smem (floats):
#define OF_M   0                   // s_m: 64 x PK (tf32 operand / y)
#define OF_B   (64*PK)             // s_B: 128 x PB (tf32 weight)
#define OF_NB  (OF_B + 128*PB)
#define SMEM_MSG_BYTES ((OF_NB + RMSG*KNN) * 4)

__global__ __launch_bounds__(256, 2) void k_msg(
    const float* __restrict__ tar,
    const float* __restrict__ W_m2, const float* __restrict__ b_m2,
    const float* __restrict__ W_a1, const float* __restrict__ b_a1,
    const float* __restrict__ W_a2, const float* __restrict__ b_a2,
    float* __restrict__ out)
{
    extern __shared__ float smem[];
    unsigned* s_m  = (unsigned*)(smem + OF_M);
    unsigned* s_B  = (unsigned*)(smem + OF_B);
    int*      s_nb = (int*)(smem + OF_NB);

    const int tid  = threadIdx.x;
    const int wid  = tid >> 5;
    const int lane = tid & 31;
    const int rg   = wid >> 2;          // 0..1 : rows rg*32..+31
    const int cg   = wid & 3;           // 0..3 : cols cg*32..+31
    const int gid  = lane >> 2;         // 0..7
    const int tig  = lane & 3;          // 0..3
    const int row0 = blockIdx.x * RMSG;

    // stage W_m2 (tf32) into s_B
    for (int i = tid; i < 128*32; i += 256) {
        int k = i >> 5, c4 = (i & 31) * 4;
        float4 w = *reinterpret_cast<const float4*>(&W_m2[k*128 + c4]);
        uint4 v = make_uint4(tf32r(w.x), tf32r(w.y), tf32r(w.z), tf32r(w.w));
        *reinterpret_cast<uint4*>(&s_B[k*PB + c4]) = v;
    }
    for (int idx = tid; idx < RMSG*KNN; idx += 256) {
        int r = idx / KNN;
        int b = (row0 + r) / NB;
        s_nb[idx] = b*NB + g_nbr[row0*KNN + idx];
    }
    __syncthreads();

    float vmax[2][4][4];
    #pragma unroll
    for (int mi = 0; mi < 2; mi++)
        #pragma unroll
        for (int ni = 0; ni < 4; ni++)
            #pragma unroll
            for (int q = 0; q < 4; q++) vmax[mi][ni][q] = -1e30f;

    for (int k = 0; k < KNN; k++) {
        // build operand: s_m[r][j] = tf32(tanh(C + A_nbr))
        #pragma unroll
        for (int it = 0; it < 8; it++) {
            int p = tid + 256*it;               // 2048 float4 slots
            int r = p >> 5, j = (p & 31) * 4;
            float4 a = *reinterpret_cast<const float4*>(&g_A[s_nb[r*KNN + k]*128 + j]);
            float4 c = *reinterpret_cast<const float4*>(&g_C[(row0 + r)*128 + j]);
            uint4 v = make_uint4(tf32r(tanha(c.x + a.x)), tf32r(tanha(c.y + a.y)),
                                 tf32r(tanha(c.z + a.z)), tf32r(tanha(c.w + a.w)));
            *reinterpret_cast<uint4*>(&s_m[r*PK + j]) = v;
        }
        __syncthreads();

        float acc[2][4][4];
        #pragma unroll
        for (int mi = 0; mi < 2; mi++)
            #pragma unroll
            for (int ni = 0; ni < 4; ni++)
                #pragma unroll
                for (int q = 0; q < 4; q++) acc[mi][ni][q] = 0.f;

        #pragma unroll
        for (int ks = 0; ks < 16; ks++) {
            int k0 = ks * 8;
            unsigned a[2][4];
            #pragma unroll
            for (int mi = 0; mi < 2; mi++) {
                int r = rg*32 + mi*16 + gid;
                a[mi][0] = s_m[r*PK + k0 + tig];
                a[mi][1] = s_m[(r+8)*PK + k0 + tig];
                a[mi][2] = s_m[r*PK + k0 + 4 + tig];
                a[mi][3] = s_m[(r+8)*PK + k0 + 4 + tig];
            }
            #pragma unroll
            for (int ni = 0; ni < 4; ni++) {
                int col = cg*32 + ni*8 + gid;
                unsigned b0 = s_B[(k0 + tig)*PB + col];
                unsigned b1 = s_B[(k0 + 4 + tig)*PB + col];
                MMA_TF32(acc[0][ni][0], acc[0][ni][1], acc[0][ni][2], acc[0][ni][3],
                         a[0][0], a[0][1], a[0][2], a[0][3], b0, b1);
                MMA_TF32(acc[1][ni][0], acc[1][ni][1], acc[1][ni][2], acc[1][ni][3],
                         a[1][0], a[1][1], a[1][2], a[1][3], b0, b1);
            }
        }
        #pragma unroll
        for (int mi = 0; mi < 2; mi++)
            #pragma unroll
            for (int ni = 0; ni < 4; ni++)
                #pragma unroll
                for (int q = 0; q < 4; q++)
                    vmax[mi][ni][q] = fmaxf(vmax[mi][ni][q], acc[mi][ni][q]);
        __syncthreads();
    }

    // x = tanh(vmax + b_m2) -> s_m (tf32, [row][col] == [row][k] for next GEMM)
    #pragma unroll
    for (int mi = 0; mi < 2; mi++)
        #pragma unroll
        for (int ni = 0; ni < 4; ni++)
            #pragma unroll
            for (int q = 0; q < 4; q++) {
                int row = rg*32 + mi*16 + gid + ((q >= 2) ? 8 : 0);
                int col = cg*32 + ni*8 + 2*tig + (q & 1);
                float xv = tanha(vmax[mi][ni][q] + b_m2[col]);
                s_m[row*PK + col] = tf32r(xv);
            }
    // stage W_a1 into s_B
    for (int i = tid; i < 128*32; i += 256) {
        int k2 = i >> 5, c4 = (i & 31) * 4;
        float4 w = *reinterpret_cast<const float4*>(&W_a1[k2*128 + c4]);
        uint4 v = make_uint4(tf32r(w.x), tf32r(w.y), tf32r(w.z), tf32r(w.w));
        *reinterpret_cast<uint4*>(&s_B[k2*PB + c4]) = v;
    }
    __syncthreads();

    // y-GEMM
    float acc[2][4][4];
    #pragma unroll
    for (int mi = 0; mi < 2; mi++)
        #pragma unroll
        for (int ni = 0; ni < 4; ni++)
            #pragma unroll
            for (int q = 0; q < 4; q++) acc[mi][ni][q] = 0.f;
    #pragma unroll
    for (int ks = 0; ks < 16; ks++) {
        int k0 = ks * 8;
        unsigned a[2][4];
        #pragma unroll
        for (int mi = 0; mi < 2; mi++) {
            int r = rg*32 + mi*16 + gid;
            a[mi][0] = s_m[r*PK + k0 + tig];
            a[mi][1] = s_m[(r+8)*PK + k0 + tig];
            a[mi][2] = s_m[r*PK + k0 + 4 + tig];
            a[mi][3] = s_m[(r+8)*PK + k0 + 4 + tig];
        }
        #pragma unroll
        for (int ni = 0; ni < 4; ni++) {
            int col = cg*32 + ni*8 + gid;
            unsigned b0 = s_B[(k0 + tig)*PB + col];
            unsigned b1 = s_B[(k0 + 4 + tig)*PB + col];
            MMA_TF32(acc[0][ni][0], acc[0][ni][1], acc[0][ni][2], acc[0][ni][3],
                     a[0][0], a[0][1], a[0][2], a[0][3], b0, b1);
            MMA_TF32(acc[1][ni][0], acc[1][ni][1], acc[1][ni][2], acc[1][ni][3],
                     a[1][0], a[1][1], a[1][2], a[1][3], b0, b1);
        }
    }
    __syncthreads();     // all x reads done before overwriting s_m with y

    // y = tanh(acc + b_a1) -> s_y (float, [row][col])
    float* s_y = (float*)s_m;
    #pragma unroll
    for (int mi = 0; mi < 2; mi++)
        #pragma unroll
        for (int ni = 0; ni < 4; ni++)
            #pragma unroll
            for (int q = 0; q < 4; q++) {
                int row = rg*32 + mi*16 + gid + ((q >= 2) ? 8 : 0);
                int col = cg*32 + ni*8 + 2*tig + (q & 1);
                s_y[row*PK + col] = tanha(acc[mi][ni][q] + b_a1[col]);
            }
    __syncthreads();

    // final 128 -> 4, exact squashing (64 rows x 4 outs = 256 threads)
    {
        int r = tid >> 2, o = tid & 3;
        float s = b_a2[o];
        #pragma unroll 4
        for (int kk = 0; kk < 128; kk++) s += s_y[r*PK + kk] * W_a2[kk*4 + o];
        int row = row0 + r;
        int b = row / NB, n = row - b*NB;
        if (o < 2) {
            float tv = tar[row*2 + o];
            out[b*60 + 2*n + o] = 0.3f*tanhf(s) + 0.3f*tanhf(tv);
        } else {
            float t = tanhf(s);
            out[BSZ*60 + b*60 + 2*n + (o-2)] = expf(3.5f*t - 1.5f);
        }
    }
}

// ---------------- launch ----------------
extern "C" void kernel_launch(void* const* d_in, const int* in_sizes, int n_in,
                              void* d_out, int out_size)
{
    const float* state_inp = (const float*)d_in[0];
    const float* tar       = (const float*)d_in[1];
    const float* W_in1     = (const float*)d_in[2];
    const float* b_in1     = (const float*)d_in[3];
    const float* W_in2     = (const float*)d_in[4];
    const float* b_in2     = (const float*)d_in[5];
    const float* emb_tab   = (const float*)d_in[6];
    const float* W_emb     = (const float*)d_in[7];
    const float* b_emb     = (const float*)d_in[8];
    const float* W_m1      = (const float*)d_in[9];
    const float* b_m1      = (const float*)d_in[10];
    const float* W_m2      = (const float*)d_in[11];
    const float* b_m2      = (const float*)d_in[12];
    const float* W_a1      = (const float*)d_in[13];
    const float* b_a1      = (const float*)d_in[14];
    const float* W_a2      = (const float*)d_in[15];
    const float* b_a2      = (const float*)d_in[16];
    float* out = (float*)d_out;

    cudaFuncSetAttribute(k_msg, cudaFuncAttributeMaxDynamicSharedMemorySize, SMEM_MSG_BYTES);

    k_setup<<<64, 256>>>(emb_tab, W_emb, b_emb, W_m1);
    k_knn<<<BSZ, 32>>>(state_inp);
    k_feat<<<NROWS/32, 256>>>(state_inp, tar, W_in1, b_in1, W_in2, b_in2, b_m1);
    k_msg<<<NROWS/RMSG, 256, SMEM_MSG_BYTES>>>(tar, W_m2, b_m2, W_a1, b_a1, W_a2, b_a2, out);
}